// round 10
// baseline (speedup 1.0000x reference)
#include <cuda_runtime.h>
#include <cuda_bf16.h>
#include <math.h>
#include <stdint.h>

#define HID 256
#define MAXN 100000
#define MAXK 384

// ---------------- scratch (static device globals: no allocation allowed) ----
static __device__ float g_bufH[(size_t)MAXN * HID];   // h = A@W
static __device__ float g_bufA[(size_t)MAXN * HID];   // agg
static __device__ int   g_deg[MAXN];
static __device__ float g_dinv[MAXN];
static __device__ float g_sum[HID];
static __device__ float g_sumsq[HID];
static __device__ float g_scale[HID];
static __device__ float g_shift[HID];
// pre-split bf16 A operands (reused across layers)
static __device__ __nv_bfloat16 g_Ah[(size_t)MAXN * MAXK];
static __device__ __nv_bfloat16 g_Al[(size_t)MAXN * MAXK];
// split-bf16 transposed weights: [N=HID][K] row-major (= .col operand for mma)
static __device__ __nv_bfloat16 g_B1h[(size_t)HID * MAXK];
static __device__ __nv_bfloat16 g_B1l[(size_t)HID * MAXK];
static __device__ __nv_bfloat16 g_B2h[(size_t)HID * HID];
static __device__ __nv_bfloat16 g_B2l[(size_t)HID * HID];

// ---------------- helpers ----------------------------------------------------
__device__ __forceinline__ uint32_t smem_u32(const void* p) {
    uint32_t a;
    asm("{ .reg .u64 t; cvta.to.shared.u64 t, %1; cvt.u32.u64 %0, t; }"
        : "=r"(a) : "l"(p));
    return a;
}
__device__ __forceinline__ uint32_t pack2(float a, float b) {
    __nv_bfloat162 t = __floats2bfloat162_rn(a, b);
    return *reinterpret_cast<uint32_t*>(&t);
}
__device__ __forceinline__ void cpa16(uint32_t dst, const void* src, int srcbytes) {
    asm volatile("cp.async.cg.shared.global [%0], [%1], 16, %2;"
                 :: "r"(dst), "l"(src), "r"(srcbytes) : "memory");
}
#define CP_COMMIT() asm volatile("cp.async.commit_group;" ::: "memory")
#define CP_WAIT1()  asm volatile("cp.async.wait_group 1;" ::: "memory")

#define LDSM4(r, a) \
    asm volatile("ldmatrix.sync.aligned.m8n8.x4.shared.b16 {%0,%1,%2,%3}, [%4];" \
                 : "=r"((r)[0]), "=r"((r)[1]), "=r"((r)[2]), "=r"((r)[3]) : "r"(a))

#define MMA16816(c, a, b0, b1) \
    asm volatile("mma.sync.aligned.m16n8k16.row.col.f32.bf16.bf16.f32 " \
                 "{%0,%1,%2,%3},{%4,%5,%6,%7},{%8,%9},{%0,%1,%2,%3};" \
                 : "+f"((c)[0]), "+f"((c)[1]), "+f"((c)[2]), "+f"((c)[3]) \
                 : "r"((a)[0]), "r"((a)[1]), "r"((a)[2]), "r"((a)[3]), \
                   "r"(b0), "r"(b1))

// ---------------- degree ----------------------------------------------------
__global__ void k_deg_init(int N) {
    int i = blockIdx.x * blockDim.x + threadIdx.x;
    if (i < N) g_deg[i] = 1;                 // self-loop
}
__global__ void k_deg_count(const int* __restrict__ dst, int E) {
    int e = blockIdx.x * blockDim.x + threadIdx.x;
    if (e < E) atomicAdd(&g_deg[dst[e]], 1);
}
__global__ void k_dinv(int N) {
    int i = blockIdx.x * blockDim.x + threadIdx.x;
    if (i < N) g_dinv[i] = rsqrtf((float)g_deg[i]);
}

// ---------------- weight transpose + bf16 split -----------------------------
__global__ void k_convB(const float* __restrict__ B, __nv_bfloat16* __restrict__ th,
                        __nv_bfloat16* __restrict__ tl, int K) {
    int i = blockIdx.x * blockDim.x + threadIdx.x;
    if (i >= K * HID) return;
    int k = i / HID, n = i % HID;
    float v = B[i];
    float h = __bfloat162float(__float2bfloat16_rn(v));
    th[(size_t)n * K + k] = __float2bfloat16_rn(h);
    tl[(size_t)n * K + k] = __float2bfloat16_rn(v - h);
}

// ---------------- A split: f32 -> bf16 hi/lo --------------------------------
// mode 0: plain split (layer-1 input x)
// mode 1: apply BN scale/shift + relu first (layer-2 input = BN(agg1))
template <int MODE>
__global__ void k_prep(const float* __restrict__ in, __nv_bfloat16* __restrict__ oh,
                       __nv_bfloat16* __restrict__ ol, long total4) {
    long i4 = (long)blockIdx.x * blockDim.x + threadIdx.x;
    if (i4 >= total4) return;
    float4 v = *(const float4*)&in[i4 * 4];
    if (MODE == 1) {
        int col4 = ((int)i4 & 63) * 4;      // HID/4 = 64 float4 per row
        float4 a = *(const float4*)&g_scale[col4];
        float4 c = *(const float4*)&g_shift[col4];
        v.x = fmaxf(fmaf(v.x, a.x, c.x), 0.0f);
        v.y = fmaxf(fmaf(v.y, a.y, c.y), 0.0f);
        v.z = fmaxf(fmaf(v.z, a.z, c.z), 0.0f);
        v.w = fmaxf(fmaf(v.w, a.w, c.w), 0.0f);
    }
    float hx = __bfloat162float(__float2bfloat16_rn(v.x));
    float hy = __bfloat162float(__float2bfloat16_rn(v.y));
    float hz = __bfloat162float(__float2bfloat16_rn(v.z));
    float hw = __bfloat162float(__float2bfloat16_rn(v.w));
    uint2 ph = make_uint2(pack2(hx, hy), pack2(hz, hw));
    uint2 pl = make_uint2(pack2(v.x - hx, v.y - hy), pack2(v.z - hz, v.w - hw));
    *(uint2*)&oh[i4 * 4] = ph;
    *(uint2*)&ol[i4 * 4] = pl;
}

// ---------------- warp-MMA GEMM: C[M,256] = A[M,K] @ B[K,256] ---------------
// CTA 128x128, 8 warps (warp tile 32x64), BK=32, 3-stage cp.async pipeline.
// A pre-split bf16 hi/lo in gmem. Split-bf16: 3 mma products for ~fp32 accuracy.
// Smem stride 40 bf16 (80B): conflict-free ldmatrix, 16B-aligned rows.
// Epilogue optionally fuses agg-init: AGG = bias + h * dinv^2.
#define PAD 40
#define OAH 0
#define OAL 10240
#define OBH 20480
#define OBL 30720
#define STG_SZ 40960
#define NSTG 3
#define SM_TOT (NSTG * STG_SZ)

__global__ __launch_bounds__(256, 1)
void k_gemm_mma(const __nv_bfloat16* __restrict__ Ah,
                const __nv_bfloat16* __restrict__ Al,
                const __nv_bfloat16* __restrict__ Bth,
                const __nv_bfloat16* __restrict__ Btl,
                float* __restrict__ C, float* __restrict__ AGG,
                const float* __restrict__ bias, int M, int K) {
    extern __shared__ char smem[];
    const uint32_t sb = smem_u32(smem);
    const int tid = threadIdx.x;
    const int lane = tid & 31;
    const int wid = tid >> 5;
    const int m0 = blockIdx.x * 128;
    const int n0 = blockIdx.y * 128;
    const int m0w = (wid & 3) * 32;
    const int n0w = (wid >> 2) * 64;

    // cp.async mapping: thread -> row tid/2, cols (tid&1)*16 + {0,8}
    const int row = tid >> 1;
    const int cg  = (tid & 1) * 16;
    const int asz = ((m0 + row) < M) ? 16 : 0;
    const __nv_bfloat16* ahp = Ah  + (size_t)(m0 + row) * K + cg;
    const __nv_bfloat16* alp = Al  + (size_t)(m0 + row) * K + cg;
    const __nv_bfloat16* bhp = Bth + (size_t)(n0 + row) * K + cg;
    const __nv_bfloat16* blp = Btl + (size_t)(n0 + row) * K + cg;
    const uint32_t soff = (uint32_t)(row * PAD + cg) * 2;

    // ldmatrix base offsets (within a stage)
    const int lrow = lane & 15;
    const int lcol = (lane >> 4) * 8;
    const uint32_t aB = OAH + (uint32_t)((m0w + lrow) * PAD + lcol) * 2;
    const uint32_t bB = OBH + (uint32_t)((n0w + lrow) * PAD + lcol) * 2;

    float acc[2][8][4];
#pragma unroll
    for (int i = 0; i < 2; i++)
#pragma unroll
        for (int j = 0; j < 8; j++)
#pragma unroll
            for (int q = 0; q < 4; q++) acc[i][j][q] = 0.0f;

    const int nch = K >> 5;

    // prologue: issue chunks 0,1
#pragma unroll
    for (int c = 0; c < 2; c++) {
        const uint32_t st = sb + (uint32_t)c * STG_SZ + soff;
        const int k0 = c * 32;
        cpa16(st + OAH,      ahp + k0,     asz);
        cpa16(st + OAH + 16, ahp + k0 + 8, asz);
        cpa16(st + OAL,      alp + k0,     asz);
        cpa16(st + OAL + 16, alp + k0 + 8, asz);
        cpa16(st + OBH,      bhp + k0,     16);
        cpa16(st + OBH + 16, bhp + k0 + 8, 16);
        cpa16(st + OBL,      blp + k0,     16);
        cpa16(st + OBL + 16, blp + k0 + 8, 16);
        CP_COMMIT();
    }

    uint32_t stg = 0;          // stage byte offset of chunk c
    uint32_t stgN = 2 * STG_SZ; // stage byte offset of chunk c+2
    for (int c = 0; c < nch; c++) {
        CP_WAIT1();
        __syncthreads();

        // issue chunk c+2 into the stage consumed at c-1
        if (c + 2 < nch) {
            const uint32_t st = sb + stgN + soff;
            const int k0 = (c + 2) * 32;
            cpa16(st + OAH,      ahp + k0,     asz);
            cpa16(st + OAH + 16, ahp + k0 + 8, asz);
            cpa16(st + OAL,      alp + k0,     asz);
            cpa16(st + OAL + 16, alp + k0 + 8, asz);
            cpa16(st + OBH,      bhp + k0,     16);
            cpa16(st + OBH + 16, bhp + k0 + 8, 16);
            cpa16(st + OBL,      blp + k0,     16);
            cpa16(st + OBL + 16, blp + k0 + 8, 16);
            CP_COMMIT();
        }

        // compute on stage of chunk c
        const uint32_t base = sb + stg;
#pragma unroll
        for (int kk = 0; kk < 2; kk++) {
            const uint32_t ko = (uint32_t)(kk * 16 * 2);
            uint32_t ah[2][4], al[2][4];
            LDSM4(ah[0], base + aB + ko);
            LDSM4(ah[1], base + aB + ko + 16 * PAD * 2);
            LDSM4(al[0], base + aB + ko + (OAL - OAH));
            LDSM4(al[1], base + aB + ko + (OAL - OAH) + 16 * PAD * 2);
#pragma unroll
            for (int ni = 0; ni < 4; ni++) {
                uint32_t bh[4], bl[4];
                const uint32_t bo = base + bB + ko + (uint32_t)(ni * 16 * PAD * 2);
                LDSM4(bh, bo);
                LDSM4(bl, bo + (OBL - OBH));
#pragma unroll
                for (int mi = 0; mi < 2; mi++) {
                    MMA16816(acc[mi][2 * ni],     ah[mi], bh[0], bh[2]);
                    MMA16816(acc[mi][2 * ni],     ah[mi], bl[0], bl[2]);
                    MMA16816(acc[mi][2 * ni],     al[mi], bh[0], bh[2]);
                    MMA16816(acc[mi][2 * ni + 1], ah[mi], bh[1], bh[3]);
                    MMA16816(acc[mi][2 * ni + 1], ah[mi], bl[1], bl[3]);
                    MMA16816(acc[mi][2 * ni + 1], al[mi], bh[1], bh[3]);
                }
            }
        }
        __syncthreads();
        stg  += STG_SZ; if (stg  == NSTG * STG_SZ) stg  = 0;
        stgN += STG_SZ; if (stgN == NSTG * STG_SZ) stgN = 0;
    }

    // epilogue: write h, and fused agg-init: AGG = bias + h*dinv^2
    const int colbase = n0 + n0w + (lane & 3) * 2;
#pragma unroll
    for (int mi = 0; mi < 2; mi++) {
#pragma unroll
        for (int half = 0; half < 2; half++) {
            const int r = m0 + m0w + mi * 16 + (lane >> 2) + half * 8;
            if (r < M) {
                float* crow = &C[(size_t)r * HID + colbase];
                float* arow = &AGG[(size_t)r * HID + colbase];
                const float dv = g_dinv[r];
                const float s = dv * dv;
#pragma unroll
                for (int nj = 0; nj < 8; nj++) {
                    float vx = acc[mi][nj][half * 2];
                    float vy = acc[mi][nj][half * 2 + 1];
                    *(float2*)(crow + nj * 8) = make_float2(vx, vy);
                    float2 bv = *(const float2*)&bias[colbase + nj * 8];
                    *(float2*)(arow + nj * 8) =
                        make_float2(fmaf(vx, s, bv.x), fmaf(vy, s, bv.y));
                }
            }
        }
    }
}

// ---------------- scatter ----------------------------------------------------
__global__ void k_scatter(const float* __restrict__ h, float* __restrict__ agg,
                          const int* __restrict__ src, const int* __restrict__ dst,
                          int E) {
    long t = (long)blockIdx.x * blockDim.x + threadIdx.x;
    int e = (int)(t >> 6);
    if (e >= E) return;
    int j = ((int)t & 63) * 4;
    int s = src[e];
    int d = dst[e];
    float coef = g_dinv[s] * g_dinv[d];
    float4 hv = *(const float4*)&h[(size_t)s * HID + j];
    float vx = hv.x * coef, vy = hv.y * coef, vz = hv.z * coef, vw = hv.w * coef;
    float* p = &agg[(size_t)d * HID + j];
    asm volatile("red.global.add.v4.f32 [%0], {%1, %2, %3, %4};"
                 :: "l"(p), "f"(vx), "f"(vy), "f"(vz), "f"(vw) : "memory");
}

// ---------------- batchnorm -------------------------------------------------
__global__ void k_bn_zero() {
    int c = threadIdx.x;
    g_sum[c] = 0.0f;
    g_sumsq[c] = 0.0f;
}

__global__ void k_bn_stats(const float* __restrict__ h, int N) {
    int col = threadIdx.x;
    float s = 0.0f, ss = 0.0f;
    for (int r = blockIdx.x; r < N; r += gridDim.x) {
        float v = h[(size_t)r * HID + col];
        s += v;
        ss += v * v;
    }
    atomicAdd(&g_sum[col], s);
    atomicAdd(&g_sumsq[col], ss);
}

__global__ void k_bn_finalize(const float* __restrict__ gamma,
                              const float* __restrict__ beta, float Nf) {
    int c = threadIdx.x;
    float mu = g_sum[c] / Nf;
    float var = g_sumsq[c] / Nf - mu * mu;
    var = fmaxf(var, 0.0f);
    float a = gamma[c] * rsqrtf(var + 1e-5f);
    g_scale[c] = a;
    g_shift[c] = beta[c] - a * mu;
}

__global__ void k_bn_apply_relu(const float* __restrict__ in, float* __restrict__ out,
                                long total4) {
    long i4 = (long)blockIdx.x * blockDim.x + threadIdx.x;
    if (i4 >= total4) return;
    int col4 = ((int)i4 & 63) * 4;
    float4 v = *(const float4*)&in[i4 * 4];
    float4 a = *(const float4*)&g_scale[col4];
    float4 c = *(const float4*)&g_shift[col4];
    float4 o;
    o.x = fmaxf(fmaf(v.x, a.x, c.x), 0.0f);
    o.y = fmaxf(fmaf(v.y, a.y, c.y), 0.0f);
    o.z = fmaxf(fmaf(v.z, a.z, c.z), 0.0f);
    o.w = fmaxf(fmaf(v.w, a.w, c.w), 0.0f);
    *(float4*)&out[i4 * 4] = o;
}

// ---------------- launch ----------------------------------------------------
extern "C" void kernel_launch(void* const* d_in, const int* in_sizes, int n_in,
                              void* d_out, int out_size) {
    const float* x   = (const float*)d_in[0];
    const int*   ei  = (const int*)  d_in[1];
    const float* W1  = (const float*)d_in[2];
    const float* b1  = (const float*)d_in[3];
    const float* gm1 = (const float*)d_in[4];
    const float* be1 = (const float*)d_in[5];
    const float* W2  = (const float*)d_in[6];
    const float* b2  = (const float*)d_in[7];
    const float* gm2 = (const float*)d_in[8];
    const float* be2 = (const float*)d_in[9];

    const int H  = in_sizes[3];            // 256
    const int K1 = in_sizes[2] / H;        // 384
    const int N  = in_sizes[0] / K1;       // 100000
    const int E  = in_sizes[1] / 2;        // 800000
    const int* src = ei;
    const int* dst = ei + E;

    float* bufH;  float* bufA;
    __nv_bfloat16 *Ah, *Al, *b1h, *b1l, *b2h, *b2l;
    cudaGetSymbolAddress((void**)&bufH, g_bufH);
    cudaGetSymbolAddress((void**)&bufA, g_bufA);
    cudaGetSymbolAddress((void**)&Ah, g_Ah);
    cudaGetSymbolAddress((void**)&Al, g_Al);
    cudaGetSymbolAddress((void**)&b1h, g_B1h);
    cudaGetSymbolAddress((void**)&b1l, g_B1l);
    cudaGetSymbolAddress((void**)&b2h, g_B2h);
    cudaGetSymbolAddress((void**)&b2l, g_B2l);
    float* out = (float*)d_out;

    cudaFuncSetAttribute(k_gemm_mma, cudaFuncAttributeMaxDynamicSharedMemorySize, SM_TOT);

    const long total4  = (long)N * H / 4;
    const long total4x = (long)N * K1 / 4;
    const int  ew      = (int)((total4 + 255) / 256);
    const int  ewx     = (int)((total4x + 255) / 256);
    const int  scat_b  = (int)(((long)E * 64 + 255) / 256);
    dim3 gg((N + 127) / 128, H / 128);

    // one-time prep
    k_deg_init<<<(N + 255) / 256, 256>>>(N);
    k_deg_count<<<(E + 255) / 256, 256>>>(dst, E);
    k_dinv<<<(N + 255) / 256, 256>>>(N);
    k_convB<<<(K1 * H + 255) / 256, 256>>>(W1, b1h, b1l, K1);
    k_convB<<<(H * H + 255) / 256, 256>>>(W2, b2h, b2l, H);

    // ---- layer 1 ----
    k_prep<0><<<ewx, 256>>>(x, Ah, Al, total4x);
    k_gemm_mma<<<gg, 256, SM_TOT>>>(Ah, Al, b1h, b1l, bufH, bufA, b1, N, K1);
    k_scatter<<<scat_b, 256>>>(bufH, bufA, src, dst, E);
    k_bn_zero<<<1, 256>>>();
    k_bn_stats<<<512, 256>>>(bufA, N);
    k_bn_finalize<<<1, 256>>>(gm1, be1, (float)N);

    // ---- layer 2 (BN+relu fused into A-prep) ----
    k_prep<1><<<ew, 256>>>(bufA, Ah, Al, total4);
    k_gemm_mma<<<gg, 256, SM_TOT>>>(Ah, Al, b2h, b2l, bufH, out, b2, N, H);
    k_scatter<<<scat_b, 256>>>(bufH, out, src, dst, E);
    k_bn_zero<<<1, 256>>>();
    k_bn_stats<<<512, 256>>>(out, N);
    k_bn_finalize<<<1, 256>>>(gm2, be2, (float)N);
    k_bn_apply_relu<<<ew, 256>>>(out, out, total4);
}